// round 9
// baseline (speedup 1.0000x reference)
#include <cuda_runtime.h>
#include <cstdint>

// SpikeLoss: loss = 0.5 * sum( (outputs - psp(target))^2 ), tau = 5
// [32,256,4,4,100] -> 131072 rows x 100 steps (rows contiguous, 400 B).
// Persistent blocks; double-buffered cp.async smem staging (no RF cost ->
// full occupancy AND full memory overlap). One warp scans one row per
// iteration via uniform-multiplier Kogge-Stone. Deterministic fused
// reduction via last-block ticket.

#define T_STEPS   100
#define ROW_V     (T_STEPS / 4)     // 25 float4 per row
#define TILE      16                // rows staged per iteration per block
#define BLOCK     512
#define WPB       (BLOCK / 32)      // 16 warps = TILE rows
#define GRID      592
#define TILE_V    (TILE * ROW_V)    // 400 float4 per array per stage

__device__ float        g_partials[1024];
__device__ unsigned int g_count = 0;

__device__ __forceinline__ void cp16(void* smem, const void* gmem) {
    uint32_t s = (uint32_t)__cvta_generic_to_shared(smem);
    asm volatile("cp.async.cg.shared.global [%0], [%1], 16;" :: "r"(s), "l"(gmem));
}
__device__ __forceinline__ void cp_commit() {
    asm volatile("cp.async.commit_group;");
}
__device__ __forceinline__ void cp_wait1() {
    asm volatile("cp.async.wait_group 1;");
}
__device__ __forceinline__ void cp_wait0() {
    asm volatile("cp.async.wait_group 0;");
}

// Per-lane loss contribution for one row held warp-wide (lane i = steps 4i..4i+3).
__device__ __forceinline__ float row_loss(float4 x, float4 o, int lane)
{
    const float D  = 0.8f, IT = 0.2f;
    const float C0 = 0.4096f;
    const float C1 = 0.16777216f;
    const float C2 = 2.8147497671e-2f;
    const float C3 = 7.9228162514e-4f;
    const float C4 = 6.2771017354e-7f;

    // local 4-step scan (zero init)
    float b = fmaf(D, fmaf(D, fmaf(D, x.x, x.y), x.z), x.w);

    // Kogge-Stone with compile-time uniform multipliers
    float p;
    p = __shfl_up_sync(0xFFFFFFFFu, b, 1);  if (lane >= 1)  b = fmaf(C0, p, b);
    p = __shfl_up_sync(0xFFFFFFFFu, b, 2);  if (lane >= 2)  b = fmaf(C1, p, b);
    p = __shfl_up_sync(0xFFFFFFFFu, b, 4);  if (lane >= 4)  b = fmaf(C2, p, b);
    p = __shfl_up_sync(0xFFFFFFFFu, b, 8);  if (lane >= 8)  b = fmaf(C3, p, b);
    p = __shfl_up_sync(0xFFFFFFFFu, b, 16); if (lane >= 16) b = fmaf(C4, p, b);

    // exclusive carry
    float syn = __shfl_up_sync(0xFFFFFFFFu, b, 1);
    if (lane == 0) syn = 0.0f;

    float acc = 0.0f, d;
    syn = fmaf(syn, D, x.x); d = fmaf(-syn, IT, o.x); acc = fmaf(d, d, acc);
    syn = fmaf(syn, D, x.y); d = fmaf(-syn, IT, o.y); acc = fmaf(d, d, acc);
    syn = fmaf(syn, D, x.z); d = fmaf(-syn, IT, o.z); acc = fmaf(d, d, acc);
    syn = fmaf(syn, D, x.w); d = fmaf(-syn, IT, o.w); acc = fmaf(d, d, acc);
    return (lane < ROW_V) ? acc : 0.0f;
}

__global__ void __launch_bounds__(BLOCK, 4)
spike_loss_cpasync(const float* __restrict__ outputs,
                   const float* __restrict__ target,
                   float* __restrict__ out,
                   int rows)
{
    __shared__ __align__(16) float4 s_x[2][TILE_V];
    __shared__ __align__(16) float4 s_o[2][TILE_V];
    __shared__ float warp_sums[WPB];
    __shared__ int   is_last;

    const int tid  = threadIdx.x;
    const int lane = tid & 31;
    const int wid  = tid >> 5;

    const float4* __restrict__ x4 = reinterpret_cast<const float4*>(target);
    const float4* __restrict__ o4 = reinterpret_cast<const float4*>(outputs);

    const int ntiles = rows / TILE;     // whole tiles (8192 for given shape)
    float acc = 0.0f;

    // ---- prologue: stage first tile into buffer 0 ----
    int t = blockIdx.x;
    if (t < ntiles) {
        const size_t base = (size_t)t * TILE_V;
        #pragma unroll
        for (int c = tid; c < 2 * TILE_V; c += BLOCK) {
            if (c < TILE_V) cp16(&s_x[0][c], x4 + base + c);
            else            cp16(&s_o[0][c - TILE_V], o4 + base + (c - TILE_V));
        }
    }
    cp_commit();

    int buf = 0;
    for (; t < ntiles; t += GRID, buf ^= 1) {
        // ---- prefetch next tile into other buffer ----
        const int tn = t + GRID;
        if (tn < ntiles) {
            const size_t base = (size_t)tn * TILE_V;
            #pragma unroll
            for (int c = tid; c < 2 * TILE_V; c += BLOCK) {
                if (c < TILE_V) cp16(&s_x[buf ^ 1][c], x4 + base + c);
                else            cp16(&s_o[buf ^ 1][c - TILE_V], o4 + base + (c - TILE_V));
            }
        }
        cp_commit();

        // ---- wait for current tile, compute ----
        cp_wait1();
        __syncthreads();

        float4 x = s_x[buf][wid * ROW_V + (lane < ROW_V ? lane : 0)];
        float4 o = s_o[buf][wid * ROW_V + (lane < ROW_V ? lane : 0)];
        acc += row_loss(x, o, lane);

        __syncthreads();   // all reads done before this buffer is re-staged
    }
    cp_wait0();

    // ---- leftover rows (rows % TILE): block 0, direct global loads ----
    if (blockIdx.x == 0) {
        const int r = ntiles * TILE + wid;
        if (r < rows) {
            float4 x = make_float4(0.f,0.f,0.f,0.f), o = x;
            if (lane < ROW_V) {
                x = __ldg(&x4[(size_t)r * ROW_V + lane]);
                o = __ldg(&o4[(size_t)r * ROW_V + lane]);
            }
            acc += row_loss(x, o, lane);
        }
    }

    // ---- once-per-block deterministic reduction ----
    #pragma unroll
    for (int off = 16; off > 0; off >>= 1)
        acc += __shfl_down_sync(0xFFFFFFFFu, acc, off);
    if (lane == 0) warp_sums[wid] = acc;
    __syncthreads();

    if (tid == 0) {
        float bsum = 0.0f;
        #pragma unroll
        for (int w = 0; w < WPB; ++w) bsum += warp_sums[w];
        g_partials[blockIdx.x] = bsum;
        __threadfence();
        unsigned int ticket = atomicAdd(&g_count, 1u);
        is_last = (ticket == gridDim.x - 1) ? 1 : 0;
    }
    __syncthreads();

    // ---- last block: fixed-order finalize ----
    if (is_last) {
        const int nblocks = gridDim.x;
        float v = 0.0f;
        for (int i = tid; i < nblocks; i += BLOCK)
            v += g_partials[i];

        #pragma unroll
        for (int off = 16; off > 0; off >>= 1)
            v += __shfl_down_sync(0xFFFFFFFFu, v, off);
        if (lane == 0) warp_sums[wid] = v;
        __syncthreads();

        if (tid == 0) {
            float stot = 0.0f;
            #pragma unroll
            for (int w = 0; w < WPB; ++w) stot += warp_sums[w];
            *out = 0.5f * stot;
            g_count = 0;   // reset for graph replay
        }
    }
}

extern "C" void kernel_launch(void* const* d_in, const int* in_sizes, int n_in,
                              void* d_out, int out_size)
{
    const float* outputs = (const float*)d_in[0];
    const float* target  = (const float*)d_in[1];
    float* out = (float*)d_out;

    const int n    = in_sizes[0];
    const int rows = n / T_STEPS;   // 131072

    spike_loss_cpasync<<<GRID, BLOCK>>>(outputs, target, out, rows);
}

// round 11
// speedup vs baseline: 1.1786x; 1.1786x over previous
#include <cuda_runtime.h>
#include <cstdint>

// SpikeLoss: loss = 0.5 * sum( (outputs - psp(target))^2 ), tau = 5
// [32,256,4,4,100] -> 131072 rows x 100 steps, rows contiguous (400B each).
// Persistent grid-stride kernel (R6 structure: 32 regs, ~98% occ): one warp
// per 2 rows per iteration, lanes 0..24 hold one float4 (coalesced). Linear
// recurrence via Kogge-Stone with compile-time uniform multipliers.
// NEW: L2 prefetch of the NEXT iteration's rows (no register/occupancy cost)
// so the blocking LDGs hit L2 (~250cyc) instead of DRAM (~577cyc).
// Deterministic fused reduction via last-block ticket.

#define T_STEPS   100
#define ROW_V     (T_STEPS / 4)   // 25 float4 per row
#define BLOCK     512
#define WPB       (BLOCK / 32)    // 16 warps -> 32 rows per iteration
#define GRID      592             // 4 blocks/SM on 148 SMs
#define STRIDE    (GRID * WPB)
#define MAX_BLOCKS 1024

__device__ float        g_partials[MAX_BLOCKS];
__device__ unsigned int g_count = 0;

__device__ __forceinline__ void l2_prefetch(const void* p) {
    asm volatile("prefetch.global.L2 [%0];" :: "l"(p));
}

__global__ void __launch_bounds__(BLOCK)
spike_loss_pf(const float* __restrict__ outputs,
              const float* __restrict__ target,
              float* __restrict__ out,
              int rows)
{
    const int tid  = threadIdx.x;
    const int lane = tid & 31;
    const int wid  = tid >> 5;

    const float D  = 0.8f;    // decay = 1 - 1/tau
    const float IT = 0.2f;    // 1/tau

    // Kogge-Stone uniform multipliers: (0.8^4)^(2^r)
    const float C0 = 0.4096f;
    const float C1 = 0.16777216f;
    const float C2 = 2.8147497671e-2f;
    const float C3 = 7.9228162514e-4f;
    const float C4 = 6.2771017354e-7f;

    const bool lv = (lane < ROW_V);
    const float4* __restrict__ x4 = reinterpret_cast<const float4*>(target);
    const float4* __restrict__ o4 = reinterpret_cast<const float4*>(outputs);

    float acc = 0.0f;
    const int npairs = rows >> 1;                 // 65536 row-pairs

    for (int pair = blockIdx.x * WPB + wid; pair < npairs;
         pair += STRIDE) {

        const size_t ra = (size_t)(2 * pair) * ROW_V + lane;

        float4 xa = make_float4(0.f,0.f,0.f,0.f), oa = xa;
        float4 xb = xa, ob = xa;
        if (lv) {
            xa = __ldg(&x4[ra]);
            xb = __ldg(&x4[ra + ROW_V]);
            oa = __ldg(&o4[ra]);
            ob = __ldg(&o4[ra + ROW_V]);
        }

        // ---- L2 prefetch next iteration (no register cost) ----
        const int npair = pair + STRIDE;
        if (npair < npairs && lv) {
            const size_t rn = (size_t)(2 * npair) * ROW_V + lane;
            l2_prefetch(&x4[rn]);
            l2_prefetch(&x4[rn + ROW_V]);
            l2_prefetch(&o4[rn]);
            l2_prefetch(&o4[rn + ROW_V]);
        }

        // Local 4-step scan (zero init): b = syn after this lane's segment.
        float bA = fmaf(D, fmaf(D, fmaf(D, xa.x, xa.y), xa.z), xa.w);
        float bB = fmaf(D, fmaf(D, fmaf(D, xb.x, xb.y), xb.z), xb.w);

        // Kogge-Stone, two independent chains interleaved.
        float pA, pB;
        pA = __shfl_up_sync(0xFFFFFFFFu, bA, 1);
        pB = __shfl_up_sync(0xFFFFFFFFu, bB, 1);
        if (lane >= 1)  { bA = fmaf(C0, pA, bA); bB = fmaf(C0, pB, bB); }
        pA = __shfl_up_sync(0xFFFFFFFFu, bA, 2);
        pB = __shfl_up_sync(0xFFFFFFFFu, bB, 2);
        if (lane >= 2)  { bA = fmaf(C1, pA, bA); bB = fmaf(C1, pB, bB); }
        pA = __shfl_up_sync(0xFFFFFFFFu, bA, 4);
        pB = __shfl_up_sync(0xFFFFFFFFu, bB, 4);
        if (lane >= 4)  { bA = fmaf(C2, pA, bA); bB = fmaf(C2, pB, bB); }
        pA = __shfl_up_sync(0xFFFFFFFFu, bA, 8);
        pB = __shfl_up_sync(0xFFFFFFFFu, bB, 8);
        if (lane >= 8)  { bA = fmaf(C3, pA, bA); bB = fmaf(C3, pB, bB); }
        pA = __shfl_up_sync(0xFFFFFFFFu, bA, 16);
        pB = __shfl_up_sync(0xFFFFFFFFu, bB, 16);
        if (lane >= 16) { bA = fmaf(C4, pA, bA); bB = fmaf(C4, pB, bB); }

        // Exclusive carry-in.
        float sA = __shfl_up_sync(0xFFFFFFFFu, bA, 1);
        float sB = __shfl_up_sync(0xFFFFFFFFu, bB, 1);
        if (lane == 0) { sA = 0.0f; sB = 0.0f; }

        if (lv) {
            float d;
            sA = fmaf(sA, D, xa.x); d = fmaf(-sA, IT, oa.x); acc = fmaf(d, d, acc);
            sA = fmaf(sA, D, xa.y); d = fmaf(-sA, IT, oa.y); acc = fmaf(d, d, acc);
            sA = fmaf(sA, D, xa.z); d = fmaf(-sA, IT, oa.z); acc = fmaf(d, d, acc);
            sA = fmaf(sA, D, xa.w); d = fmaf(-sA, IT, oa.w); acc = fmaf(d, d, acc);
            sB = fmaf(sB, D, xb.x); d = fmaf(-sB, IT, ob.x); acc = fmaf(d, d, acc);
            sB = fmaf(sB, D, xb.y); d = fmaf(-sB, IT, ob.y); acc = fmaf(d, d, acc);
            sB = fmaf(sB, D, xb.z); d = fmaf(-sB, IT, ob.z); acc = fmaf(d, d, acc);
            sB = fmaf(sB, D, xb.w); d = fmaf(-sB, IT, ob.w); acc = fmaf(d, d, acc);
        }
    }

    // ---- once-per-block deterministic reduction ----
    __shared__ float warp_sums[WPB];
    __shared__ int   is_last;

    #pragma unroll
    for (int off = 16; off > 0; off >>= 1)
        acc += __shfl_down_sync(0xFFFFFFFFu, acc, off);
    if (lane == 0) warp_sums[wid] = acc;
    __syncthreads();

    if (tid == 0) {
        float bsum = 0.0f;
        #pragma unroll
        for (int w = 0; w < WPB; ++w) bsum += warp_sums[w];
        g_partials[blockIdx.x] = bsum;
        __threadfence();
        unsigned int ticket = atomicAdd(&g_count, 1u);
        is_last = (ticket == gridDim.x - 1) ? 1 : 0;
    }
    __syncthreads();

    // ---- last block: fixed-order finalize over GRID partials ----
    if (is_last) {
        const int nblocks = gridDim.x;
        float v = 0.0f;
        for (int i = tid; i < nblocks; i += BLOCK)
            v += g_partials[i];

        #pragma unroll
        for (int off = 16; off > 0; off >>= 1)
            v += __shfl_down_sync(0xFFFFFFFFu, v, off);
        if (lane == 0) warp_sums[wid] = v;
        __syncthreads();

        if (tid == 0) {
            float stot = 0.0f;
            #pragma unroll
            for (int w = 0; w < WPB; ++w) stot += warp_sums[w];
            *out = 0.5f * stot;
            g_count = 0;   // reset for graph replay
        }
    }
}

extern "C" void kernel_launch(void* const* d_in, const int* in_sizes, int n_in,
                              void* d_out, int out_size)
{
    const float* outputs = (const float*)d_in[0];
    const float* target  = (const float*)d_in[1];
    float* out = (float*)d_out;

    const int n    = in_sizes[0];
    const int rows = n / T_STEPS;   // 131072 (even -> pairs exact)

    spike_loss_pf<<<GRID, BLOCK>>>(outputs, target, out, rows);
}

// round 12
// speedup vs baseline: 1.3026x; 1.1052x over previous
#include <cuda_runtime.h>
#include <cstdint>

// SpikeLoss: loss = 0.5 * sum( (outputs - psp(target))^2 ), tau = 5
// [32,256,4,4,100] -> 131072 rows x 100 steps, rows contiguous (400B each).
// Persistent warp-per-2-rows kernel. Critical-path-only register prefetch:
// next iteration's X vectors (scan inputs) are prefetched (+8 regs only);
// O vectors are issued at the top of the iteration and consumed ~300cyc
// later (hidden by the shfl scan). All loads streaming (__ldcs).
// Kogge-Stone scan with compile-time uniform multipliers.
// Deterministic fused reduction via last-block ticket.

#define T_STEPS   100
#define ROW_V     (T_STEPS / 4)   // 25 float4 per row
#define BLOCK     512
#define WPB       (BLOCK / 32)    // 16 warps -> 32 rows per iteration
#define GRID      444             // 3 blocks/SM x 148 SMs, exact wave
#define STRIDE    (GRID * WPB)
#define MAX_BLOCKS 1024

__device__ float        g_partials[MAX_BLOCKS];
__device__ unsigned int g_count = 0;

__global__ void __launch_bounds__(BLOCK, 3)
spike_loss_xpf(const float* __restrict__ outputs,
               const float* __restrict__ target,
               float* __restrict__ out,
               int rows)
{
    const int tid  = threadIdx.x;
    const int lane = tid & 31;
    const int wid  = tid >> 5;

    const float D  = 0.8f;    // decay = 1 - 1/tau
    const float IT = 0.2f;    // 1/tau

    // Kogge-Stone uniform multipliers: (0.8^4)^(2^r)
    const float C0 = 0.4096f;
    const float C1 = 0.16777216f;
    const float C2 = 2.8147497671e-2f;
    const float C3 = 7.9228162514e-4f;
    const float C4 = 6.2771017354e-7f;

    const bool lv = (lane < ROW_V);
    const float4* __restrict__ x4 = reinterpret_cast<const float4*>(target);
    const float4* __restrict__ o4 = reinterpret_cast<const float4*>(outputs);

    float acc = 0.0f;
    const int npairs = rows >> 1;                 // 65536 row-pairs

    int pair   = blockIdx.x * WPB + wid;
    bool valid = pair < npairs;

    // ---- prologue: prefetch first iteration's X ----
    float4 xa = make_float4(0.f,0.f,0.f,0.f), xb = xa;
    if (valid && lv) {
        const size_t ra = (size_t)(2 * pair) * ROW_V + lane;
        xa = __ldcs(&x4[ra]);
        xb = __ldcs(&x4[ra + ROW_V]);
    }

    while (valid) {
        // ---- issue this iteration's O and next iteration's X up front ----
        float4 oa = make_float4(0.f,0.f,0.f,0.f), ob = oa;
        if (lv) {
            const size_t ra = (size_t)(2 * pair) * ROW_V + lane;
            oa = __ldcs(&o4[ra]);
            ob = __ldcs(&o4[ra + ROW_V]);
        }
        const int  npair  = pair + STRIDE;
        const bool nvalid = npair < npairs;
        float4 nxa = make_float4(0.f,0.f,0.f,0.f), nxb = nxa;
        if (nvalid && lv) {
            const size_t rn = (size_t)(2 * npair) * ROW_V + lane;
            nxa = __ldcs(&x4[rn]);
            nxb = __ldcs(&x4[rn + ROW_V]);
        }

        // ---- local 4-step scan on resident X (no memory wait) ----
        float bA = fmaf(D, fmaf(D, fmaf(D, xa.x, xa.y), xa.z), xa.w);
        float bB = fmaf(D, fmaf(D, fmaf(D, xb.x, xb.y), xb.z), xb.w);

        // ---- Kogge-Stone, two chains interleaved (~180 cyc, hides O flight) ----
        float pA, pB;
        pA = __shfl_up_sync(0xFFFFFFFFu, bA, 1);
        pB = __shfl_up_sync(0xFFFFFFFFu, bB, 1);
        if (lane >= 1)  { bA = fmaf(C0, pA, bA); bB = fmaf(C0, pB, bB); }
        pA = __shfl_up_sync(0xFFFFFFFFu, bA, 2);
        pB = __shfl_up_sync(0xFFFFFFFFu, bB, 2);
        if (lane >= 2)  { bA = fmaf(C1, pA, bA); bB = fmaf(C1, pB, bB); }
        pA = __shfl_up_sync(0xFFFFFFFFu, bA, 4);
        pB = __shfl_up_sync(0xFFFFFFFFu, bB, 4);
        if (lane >= 4)  { bA = fmaf(C2, pA, bA); bB = fmaf(C2, pB, bB); }
        pA = __shfl_up_sync(0xFFFFFFFFu, bA, 8);
        pB = __shfl_up_sync(0xFFFFFFFFu, bB, 8);
        if (lane >= 8)  { bA = fmaf(C3, pA, bA); bB = fmaf(C3, pB, bB); }
        pA = __shfl_up_sync(0xFFFFFFFFu, bA, 16);
        pB = __shfl_up_sync(0xFFFFFFFFu, bB, 16);
        if (lane >= 16) { bA = fmaf(C4, pA, bA); bB = fmaf(C4, pB, bB); }

        // Exclusive carry-in.
        float sA = __shfl_up_sync(0xFFFFFFFFu, bA, 1);
        float sB = __shfl_up_sync(0xFFFFFFFFu, bB, 1);
        if (lane == 0) { sA = 0.0f; sB = 0.0f; }

        // ---- finals consume O (arrived during the scan) ----
        if (lv) {
            float d;
            sA = fmaf(sA, D, xa.x); d = fmaf(-sA, IT, oa.x); acc = fmaf(d, d, acc);
            sA = fmaf(sA, D, xa.y); d = fmaf(-sA, IT, oa.y); acc = fmaf(d, d, acc);
            sA = fmaf(sA, D, xa.z); d = fmaf(-sA, IT, oa.z); acc = fmaf(d, d, acc);
            sA = fmaf(sA, D, xa.w); d = fmaf(-sA, IT, oa.w); acc = fmaf(d, d, acc);
            sB = fmaf(sB, D, xb.x); d = fmaf(-sB, IT, ob.x); acc = fmaf(d, d, acc);
            sB = fmaf(sB, D, xb.y); d = fmaf(-sB, IT, ob.y); acc = fmaf(d, d, acc);
            sB = fmaf(sB, D, xb.z); d = fmaf(-sB, IT, ob.z); acc = fmaf(d, d, acc);
            sB = fmaf(sB, D, xb.w); d = fmaf(-sB, IT, ob.w); acc = fmaf(d, d, acc);
        }

        // rotate prefetched X
        xa = nxa; xb = nxb;
        pair = npair; valid = nvalid;
    }

    // ---- once-per-block deterministic reduction ----
    __shared__ float warp_sums[WPB];
    __shared__ int   is_last;

    #pragma unroll
    for (int off = 16; off > 0; off >>= 1)
        acc += __shfl_down_sync(0xFFFFFFFFu, acc, off);
    if (lane == 0) warp_sums[wid] = acc;
    __syncthreads();

    if (tid == 0) {
        float bsum = 0.0f;
        #pragma unroll
        for (int w = 0; w < WPB; ++w) bsum += warp_sums[w];
        g_partials[blockIdx.x] = bsum;
        __threadfence();
        unsigned int ticket = atomicAdd(&g_count, 1u);
        is_last = (ticket == gridDim.x - 1) ? 1 : 0;
    }
    __syncthreads();

    // ---- last block: fixed-order finalize over GRID partials ----
    if (is_last) {
        const int nblocks = gridDim.x;
        float v = 0.0f;
        for (int i = tid; i < nblocks; i += BLOCK)
            v += g_partials[i];

        #pragma unroll
        for (int off = 16; off > 0; off >>= 1)
            v += __shfl_down_sync(0xFFFFFFFFu, v, off);
        if (lane == 0) warp_sums[wid] = v;
        __syncthreads();

        if (tid == 0) {
            float stot = 0.0f;
            #pragma unroll
            for (int w = 0; w < WPB; ++w) stot += warp_sums[w];
            *out = 0.5f * stot;
            g_count = 0;   // reset for graph replay
        }
    }
}

extern "C" void kernel_launch(void* const* d_in, const int* in_sizes, int n_in,
                              void* d_out, int out_size)
{
    const float* outputs = (const float*)d_in[0];
    const float* target  = (const float*)d_in[1];
    float* out = (float*)d_out;

    const int n    = in_sizes[0];
    const int rows = n / T_STEPS;   // 131072 (even -> pairs exact)

    spike_loss_xpf<<<GRID, BLOCK>>>(outputs, target, out, rows);
}